// round 1
// baseline (speedup 1.0000x reference)
#include <cuda_runtime.h>
#include <math.h>

#define NN 100000
#define EE 600000
#define DD 128
#define ETOT (EE + NN)

// ---------------- scratch (static device globals; no allocation) ----------------
__device__ float g_x0[NN * DD];
__device__ float g_x1[NN * DD];
__device__ float g_h [NN * DD];
__device__ float g_el[NN * 4];
__device__ float g_er[NN * 4];
__device__ int   g_rowptr[NN + 1];
__device__ int   g_cnt[NN];
__device__ int   g_csr[ETOT];

// ---------------- CSR build (dst-sorted incidence, self-loops included) ----------
__global__ void k_cnt_init() {
    int i = blockIdx.x * blockDim.x + threadIdx.x;
    if (i < NN) g_cnt[i] = 1;  // self loop
}

__global__ void k_hist(const int* __restrict__ dst) {
    int i = blockIdx.x * blockDim.x + threadIdx.x;
    if (i < EE) atomicAdd(&g_cnt[dst[i]], 1);
}

// single-block 2-phase exclusive scan of g_cnt -> g_rowptr, reset g_cnt to cursor
__global__ void k_scan() {
    __shared__ int ss[1024];
    int t = threadIdx.x;
    const int chunk = (NN + 1023) / 1024;
    int beg = t * chunk;
    int end = min(beg + chunk, NN);
    int s = 0;
    for (int i = beg; i < end; i++) s += g_cnt[i];
    ss[t] = s;
    __syncthreads();
    for (int o = 1; o < 1024; o <<= 1) {
        int v = (t >= o) ? ss[t - o] : 0;
        __syncthreads();
        ss[t] += v;
        __syncthreads();
    }
    int run = (t == 0) ? 0 : ss[t - 1];
    for (int i = beg; i < end; i++) {
        int c = g_cnt[i];
        g_rowptr[i] = run;
        g_cnt[i] = run;   // cursor for scatter
        run += c;
    }
    if (t == 1023) g_rowptr[NN] = ss[1023];
}

__global__ void k_scatter(const int* __restrict__ src, const int* __restrict__ dst) {
    int i = blockIdx.x * blockDim.x + threadIdx.x;
    if (i < EE) {
        int p = atomicAdd(&g_cnt[dst[i]], 1);
        g_csr[p] = src[i];
    } else if (i < EE + NN) {
        int n = i - EE;
        int p = atomicAdd(&g_cnt[n], 1);
        g_csr[p] = n;  // self loop
    }
}

// ---------------- x init: x[n][d] = w[n]*linW[d] + linb[d] ----------------------
__global__ void k_init_x(const float* __restrict__ w,
                         const float* __restrict__ linW,
                         const float* __restrict__ linb) {
    int i = blockIdx.x * blockDim.x + threadIdx.x;
    if (i < NN * DD) {
        int n = i >> 7, d = i & 127;
        g_x0[i] = w[n] * linW[d] + linb[d];
    }
}

// ---------------- GEMM h = act(x) @ W^T fused with el/er projections ------------
// 64 rows x 128 cols per 256-thread block; 8x4 micro-tile per thread.
template <bool ACT, int INBUF>
__global__ void __launch_bounds__(256) k_gemm(const float* __restrict__ W,
                                              const float* __restrict__ al,
                                              const float* __restrict__ ar) {
    const float* __restrict__ x = INBUF ? g_x1 : g_x0;
    __shared__ float xs[64][33];
    __shared__ float ws[32][132];  // W transposed chunk: ws[k][d]
    int tx = threadIdx.x & 31;     // col group (4 cols each)
    int ty = threadIdx.x >> 5;     // row group (8 rows each)
    int row0 = blockIdx.x * 64;

    float acc[8][4];
#pragma unroll
    for (int r = 0; r < 8; r++)
#pragma unroll
        for (int c = 0; c < 4; c++) acc[r][c] = 0.f;

    for (int k0 = 0; k0 < 128; k0 += 32) {
#pragma unroll
        for (int i = threadIdx.x; i < 64 * 32; i += 256) {
            int r = i >> 5, k = i & 31;
            int row = row0 + r;
            float v = (row < NN) ? x[row * 128 + k0 + k] : 0.f;
            if (ACT) v = v >= 0.f ? v : 0.01f * v;
            xs[r][k] = v;
        }
#pragma unroll
        for (int i = threadIdx.x; i < 128 * 32; i += 256) {
            int d = i >> 5, k = i & 31;
            ws[k][d] = W[d * 128 + k0 + k];  // coalesced global read
        }
        __syncthreads();
#pragma unroll
        for (int k = 0; k < 32; k++) {
            float4 b = *(const float4*)&ws[k][tx * 4];
#pragma unroll
            for (int r = 0; r < 8; r++) {
                float a = xs[ty * 8 + r][k];
                acc[r][0] = fmaf(a, b.x, acc[r][0]);
                acc[r][1] = fmaf(a, b.y, acc[r][1]);
                acc[r][2] = fmaf(a, b.z, acc[r][2]);
                acc[r][3] = fmaf(a, b.w, acc[r][3]);
            }
        }
        __syncthreads();
    }

    int col = tx * 4;
    float4 alv = *(const float4*)&al[col];
    float4 arv = *(const float4*)&ar[col];
#pragma unroll
    for (int r = 0; r < 8; r++) {
        int row = row0 + ty * 8 + r;
        if (row < NN) {
            *(float4*)&g_h[row * 128 + col] =
                make_float4(acc[r][0], acc[r][1], acc[r][2], acc[r][3]);
            float pl = acc[r][0] * alv.x + acc[r][1] * alv.y + acc[r][2] * alv.z + acc[r][3] * alv.w;
            float pr = acc[r][0] * arv.x + acc[r][1] * arv.y + acc[r][2] * arv.z + acc[r][3] * arv.w;
#pragma unroll
            for (int o = 4; o > 0; o >>= 1) {  // reduce within 8-lane head group
                pl += __shfl_xor_sync(0xffffffffu, pl, o);
                pr += __shfl_xor_sync(0xffffffffu, pr, o);
            }
            if ((tx & 7) == 0) {
                int hh = tx >> 3;
                g_el[row * 4 + hh] = pl;
                g_er[row * 4 + hh] = pr;
            }
        }
    }
}

// ---------------- edge softmax + aggregation: one warp per dst node -------------
__device__ __forceinline__ float sel4(float4 v, int hh) {
    return (hh & 2) ? ((hh & 1) ? v.w : v.z) : ((hh & 1) ? v.y : v.x);
}

template <int OUTBUF>
__global__ void __launch_bounds__(256) k_agg(const float* __restrict__ bias) {
    float* __restrict__ xout = OUTBUF ? g_x1 : g_x0;
    int gw = (blockIdx.x * blockDim.x + threadIdx.x) >> 5;
    int lane = threadIdx.x & 31;
    if (gw >= NN) return;
    int n = gw;
    int beg = g_rowptr[n], end = g_rowptr[n + 1];
    float4 er4 = *(const float4*)&g_er[n * 4];

    // pass 1: per-head max of leaky(el[src]+er[dst]), lane-strided
    float m0 = -3.4e38f, m1 = m0, m2 = m0, m3 = m0;
    for (int j = beg + lane; j < end; j += 32) {
        int s = g_csr[j];
        float4 el4 = *(const float4*)&g_el[s * 4];
        float e0 = el4.x + er4.x; e0 = e0 >= 0.f ? e0 : 0.2f * e0;
        float e1 = el4.y + er4.y; e1 = e1 >= 0.f ? e1 : 0.2f * e1;
        float e2 = el4.z + er4.z; e2 = e2 >= 0.f ? e2 : 0.2f * e2;
        float e3 = el4.w + er4.w; e3 = e3 >= 0.f ? e3 : 0.2f * e3;
        m0 = fmaxf(m0, e0); m1 = fmaxf(m1, e1);
        m2 = fmaxf(m2, e2); m3 = fmaxf(m3, e3);
    }
#pragma unroll
    for (int o = 16; o > 0; o >>= 1) {
        m0 = fmaxf(m0, __shfl_xor_sync(0xffffffffu, m0, o));
        m1 = fmaxf(m1, __shfl_xor_sync(0xffffffffu, m1, o));
        m2 = fmaxf(m2, __shfl_xor_sync(0xffffffffu, m2, o));
        m3 = fmaxf(m3, __shfl_xor_sync(0xffffffffu, m3, o));
    }

    int hh = lane >> 3;  // head owned by this lane's 4 output columns
    float mh = (hh & 2) ? ((hh & 1) ? m3 : m2) : ((hh & 1) ? m1 : m0);
    float erh = sel4(er4, hh);

    // pass 2: whole warp walks edges together; 128-float h row coalesced.
    // Every lane in a head group computes identical p => sacc IS the full sum.
    float a0 = 0.f, a1 = 0.f, a2 = 0.f, a3 = 0.f, sacc = 0.f;
    for (int j = beg; j < end; j++) {
        int s = g_csr[j];
        float4 el4 = *(const float4*)&g_el[s * 4];
        float e = sel4(el4, hh) + erh;
        e = e >= 0.f ? e : 0.2f * e;
        float p = __expf(e - mh);
        float4 hv = *(const float4*)&g_h[s * 128 + lane * 4];
        a0 = fmaf(p, hv.x, a0); a1 = fmaf(p, hv.y, a1);
        a2 = fmaf(p, hv.z, a2); a3 = fmaf(p, hv.w, a3);
        sacc += p;
    }
    float inv = 1.f / sacc;
    int col = lane * 4;
    float4 bv = *(const float4*)&bias[col];
    float4 o = make_float4(fmaf(a0, inv, bv.x), fmaf(a1, inv, bv.y),
                           fmaf(a2, inv, bv.z), fmaf(a3, inv, bv.w));
    *(float4*)&xout[n * 128 + col] = o;
}

// ---------------- prediction head: logits[n] = x[n]·pred_W + pred_b -------------
__global__ void __launch_bounds__(256) k_pred(const float* __restrict__ pW,
                                              const float* __restrict__ pb,
                                              float* __restrict__ out) {
    int gw = (blockIdx.x * blockDim.x + threadIdx.x) >> 5;
    int lane = threadIdx.x & 31;
    if (gw >= NN) return;
    float4 xv = *(const float4*)&g_x1[gw * 128 + lane * 4];
    float4 wv = *(const float4*)&pW[lane * 4];
    float s = xv.x * wv.x + xv.y * wv.y + xv.z * wv.z + xv.w * wv.w;
#pragma unroll
    for (int o = 16; o > 0; o >>= 1) s += __shfl_xor_sync(0xffffffffu, s, o);
    if (lane == 0) out[gw] = s + pb[0];
}

// ---------------- launch --------------------------------------------------------
extern "C" void kernel_launch(void* const* d_in, const int* in_sizes, int n_in,
                              void* d_out, int out_size) {
    const float* weights = (const float*)d_in[0];
    const float* linW    = (const float*)d_in[1];
    const float* linb    = (const float*)d_in[2];
    const float* fcW     = (const float*)d_in[3];
    const float* al      = (const float*)d_in[4];
    const float* ar      = (const float*)d_in[5];
    const float* cb      = (const float*)d_in[6];
    const float* pW      = (const float*)d_in[7];
    const float* pb      = (const float*)d_in[8];
    const int*   src     = (const int*)d_in[9];
    const int*   dst     = (const int*)d_in[10];
    float* out = (float*)d_out;

    // CSR (per-launch, graph-capturable, deterministic up to fp-sum order)
    k_cnt_init<<<(NN + 255) / 256, 256>>>();
    k_hist<<<(EE + 255) / 256, 256>>>(dst);
    k_scan<<<1, 1024>>>();
    k_scatter<<<(EE + NN + 255) / 256, 256>>>(src, dst);

    k_init_x<<<(NN * DD + 255) / 256, 256>>>(weights, linW, linb);

    const int GB = (NN + 63) / 64;
    const int AB = (NN * 32 + 255) / 256;

    // layer 0: x0 -> h -> x1
    k_gemm<false, 0><<<GB, 256>>>(fcW, al, ar);
    k_agg<1><<<AB, 256>>>(cb);
    // layer 1: x1 -> h -> x0   (leaky 0.01 on input)
    k_gemm<true, 1><<<GB, 256>>>(fcW + DD * DD, al + DD, ar + DD);
    k_agg<0><<<AB, 256>>>(cb + DD);
    // layer 2: x0 -> h -> x1
    k_gemm<true, 0><<<GB, 256>>>(fcW + 2 * DD * DD, al + 2 * DD, ar + 2 * DD);
    k_agg<1><<<AB, 256>>>(cb + 2 * DD);

    k_pred<<<AB, 256>>>(pW, pb, out);
}